// round 3
// baseline (speedup 1.0000x reference)
#include <cuda_runtime.h>

// Problem constants
#define BB 128
#define DD 128
#define TT 2048
#define CC 64
#define NROWS (BB * TT)          // 262144
#define TILE_T 512
#define NTILES (TT / TILE_T)     // 4
#define DCH 32
#define NCH (DD / DCH)           // 4
#define THREADS 256
#define NWARP (THREADS / 32)
#define PITCH 33                 // conflict-free transpose pitch

// Scratch (allocation-free: __device__ globals)
__device__ float g_S[CC * DD];
__device__ float g_loss;
__device__ int   g_count[CC];

// Dynamic smem layout (bytes)
#define SM_TILE_OFF   0
#define SM_TILE_BYTES (TILE_T * PITCH * 4)                 // 67584
#define SM_ORDER_OFF  (SM_TILE_OFF + SM_TILE_BYTES)
#define SM_ORDER_BYTES (TILE_T * 2)                        // 1024
#define SM_LABS_OFF   (SM_ORDER_OFF + SM_ORDER_BYTES)
#define SM_LABS_BYTES (TILE_T)                             // 512
#define SM_HIST_OFF   (SM_LABS_OFF + SM_LABS_BYTES)        // 69120, 4B aligned
#define SM_HIST_BYTES (CC * 4)
#define SM_START_OFF  (SM_HIST_OFF + SM_HIST_BYTES)
#define SM_CUR_OFF    (SM_START_OFF + SM_HIST_BYTES)
#define SM_WLOSS_OFF  (SM_CUR_OFF + SM_HIST_BYTES)
#define SM_TOTAL      (SM_WLOSS_OFF + NWARP * 4)

__global__ void cl_init_kernel() {
    int i = blockIdx.x * blockDim.x + threadIdx.x;
    if (i < CC * DD) g_S[i] = 0.0f;
    if (i < CC)      g_count[i] = 0;
    if (i == 0)      g_loss = 0.0f;
}

__global__ __launch_bounds__(THREADS)
void cl_main_kernel(const float* __restrict__ feature,
                    const int* __restrict__ label,
                    const float* __restrict__ centers) {
    extern __shared__ char sm[];
    float*          tile    = (float*)(sm + SM_TILE_OFF);
    unsigned short* order   = (unsigned short*)(sm + SM_ORDER_OFF);
    unsigned char*  labs    = (unsigned char*)(sm + SM_LABS_OFF);
    int*            hist    = (int*)(sm + SM_HIST_OFF);
    int*            starts  = (int*)(sm + SM_START_OFF);
    int*            cursor  = (int*)(sm + SM_CUR_OFF);
    float*          wloss   = (float*)(sm + SM_WLOSS_OFF);

    const int tid  = threadIdx.x;
    const int lane = tid & 31;
    const int wid  = tid >> 5;
    const int b    = blockIdx.x / NTILES;
    const int t0   = (blockIdx.x % NTILES) * TILE_T;

    if (tid < CC) hist[tid] = 0;
    __syncthreads();

    // Load labels for this tile + histogram. Mask to [0,64) so a bad value can
    // only produce a wrong answer, never smem corruption.
    for (int i = tid; i < TILE_T; i += THREADS) {
        int l = label[b * TT + t0 + i] & (CC - 1);
        labs[i] = (unsigned char)l;
        atomicAdd(&hist[l], 1);
    }
    __syncthreads();

    // Exclusive prefix over 64 classes (serial, trivial)
    if (tid == 0) {
        int s = 0;
        #pragma unroll
        for (int c = 0; c < CC; c++) { starts[c] = s; cursor[c] = s; s += hist[c]; }
    }
    __syncthreads();

    // Counting-sort scatter: order[] holds tile-local t indices grouped by class
    for (int i = tid; i < TILE_T; i += THREADS) {
        int pos = atomicAdd(&cursor[labs[i]], 1);
        order[pos] = (unsigned short)i;
    }

    // Global counts — once per block (block covers all d internally)
    if (tid < CC) atomicAdd(&g_count[tid], hist[tid]);

    float lossacc = 0.0f;

    for (int ch = 0; ch < NCH; ch++) {
        __syncthreads();
        // Stage feature chunk [DCH x TILE_T] into transposed tile[t*PITCH + dd].
        // Global: lanes read consecutive t (coalesced). Smem store: addr = t*33+dd,
        // lanes consecutive t -> (t+dd)%32 distinct banks -> conflict-free.
        const float* fbase = feature + ((long long)b * DD + ch * DCH) * TT + t0;
        for (int e = tid; e < DCH * TILE_T; e += THREADS) {
            int dd = e >> 9;          // / TILE_T
            int t  = e & (TILE_T - 1);
            tile[t * PITCH + dd] = fbase[dd * TT + t];
        }
        __syncthreads();

        // Per-class register accumulation. Warp w owns classes w, w+8, ...
        // Lane = d-within-chunk. Read tile[t*33+lane]: banks (t+lane)%32 -> conflict-free.
        for (int c = wid; c < CC; c += NWARP) {
            const int   m   = hist[c];
            const int   st  = starts[c];
            const float cen = centers[c * DD + ch * DCH + lane];
            float s0 = 0.0f, s1 = 0.0f;
            float l0 = 0.0f, l1 = 0.0f;
            int j = 0;
            for (; j + 1 < m; j += 2) {
                int ta = order[st + j];
                int tb = order[st + j + 1];
                float va = tile[ta * PITCH + lane];
                float vb = tile[tb * PITCH + lane];
                s0 += va; s1 += vb;
                float da = va - cen, db = vb - cen;
                l0 += da * da; l1 += db * db;
            }
            if (j < m) {
                int ta = order[st + j];
                float va = tile[ta * PITCH + lane];
                s0 += va;
                float da = va - cen;
                l0 += da * da;
            }
            lossacc += l0 + l1;
            atomicAdd(&g_S[c * DD + ch * DCH + lane], s0 + s1);
        }
    }

    // Loss reduction: lane -> warp -> block -> global
    #pragma unroll
    for (int o = 16; o > 0; o >>= 1)
        lossacc += __shfl_xor_sync(0xffffffffu, lossacc, o);
    if (lane == 0) wloss[wid] = lossacc;
    __syncthreads();
    if (tid == 0) {
        float s = 0.0f;
        #pragma unroll
        for (int w = 0; w < NWARP; w++) s += wloss[w];
        atomicAdd(&g_loss, s);
    }
}

__global__ void cl_finalize_kernel(const float* __restrict__ centers,
                                   float* __restrict__ out) {
    int i = blockIdx.x * blockDim.x + threadIdx.x;
    if (i == 0) out[0] = g_loss / (float)((long long)NROWS * DD);
    if (i < CC * DD) {
        int c = i / DD;
        int cnt = g_count[c];
        float diff = (cnt > 0) ? (centers[i] - g_S[i] / (float)cnt) : 0.0f;
        out[1 + i] = diff;
    }
}

extern "C" void kernel_launch(void* const* d_in, const int* in_sizes, int n_in,
                              void* d_out, int out_size) {
    // Bind inputs by element count (robust to metadata ordering):
    //   feature 33554432, label 262144, centers 8192
    const float* feature = 0;
    const int*   label   = 0;
    const float* centers = 0;
    for (int i = 0; i < n_in; i++) {
        if (in_sizes[i] == BB * DD * TT)      feature = (const float*)d_in[i];
        else if (in_sizes[i] == BB * TT)      label   = (const int*)d_in[i];
        else if (in_sizes[i] == CC * DD)      centers = (const float*)d_in[i];
    }
    float* out = (float*)d_out;
    (void)out_size;

    cudaFuncSetAttribute(cl_main_kernel,
                         cudaFuncAttributeMaxDynamicSharedMemorySize, SM_TOTAL);

    cl_init_kernel<<<(CC * DD + 255) / 256, 256>>>();
    cl_main_kernel<<<BB * NTILES, THREADS, SM_TOTAL>>>(feature, label, centers);
    cl_finalize_kernel<<<(CC * DD + 255) / 256, 256>>>(centers, out);
}

// round 4
// speedup vs baseline: 1.2452x; 1.2452x over previous
#include <cuda_runtime.h>

// Problem constants
#define BB 128
#define DD 128
#define TT 2048
#define CC 64
#define NROWS (BB * TT)          // 262144
#define TILE_T 512
#define NTILES (TT / TILE_T)     // 4
#define DCH 32
#define NCH (DD / DCH)           // 4
#define THREADS 256
#define NWARP (THREADS / 32)
#define PITCH 33                 // conflict-free transpose pitch
#define GRID (BB * NTILES)       // 512

// Scratch (allocation-free: __device__ globals, zero-initialized at load,
// self-reset by the last block each run so graph replays are identical)
__device__ float        g_S[CC * DD];
__device__ float        g_loss;
__device__ int          g_count[CC];
__device__ unsigned int g_done;

// Dynamic smem layout (bytes)
#define SM_TILE_OFF   0
#define SM_TILE_BYTES (TILE_T * PITCH * 4)                 // 67584
#define SM_ORDER_OFF  (SM_TILE_OFF + SM_TILE_BYTES)
#define SM_ORDER_BYTES (TILE_T * 2)                        // 1024
#define SM_LABS_OFF   (SM_ORDER_OFF + SM_ORDER_BYTES)
#define SM_LABS_BYTES (TILE_T)                             // 512
#define SM_HIST_OFF   (SM_LABS_OFF + SM_LABS_BYTES)        // 4B aligned
#define SM_HIST_BYTES (CC * 4)
#define SM_START_OFF  (SM_HIST_OFF + SM_HIST_BYTES)
#define SM_CUR_OFF    (SM_START_OFF + SM_HIST_BYTES)
#define SM_WLOSS_OFF  (SM_CUR_OFF + SM_HIST_BYTES)
#define SM_WTOT_OFF   (SM_WLOSS_OFF + NWARP * 4)           // 2 ints (scan carry)
#define SM_TICK_OFF   (SM_WTOT_OFF + 8)
#define SM_TOTAL      (SM_TICK_OFF + 4)

__global__ __launch_bounds__(THREADS, 3)
void cl_fused_kernel(const float* __restrict__ feature,
                     const int* __restrict__ label,
                     const float* __restrict__ centers,
                     float* __restrict__ out) {
    extern __shared__ char sm[];
    float*          tile    = (float*)(sm + SM_TILE_OFF);
    unsigned short* order   = (unsigned short*)(sm + SM_ORDER_OFF);
    unsigned char*  labs    = (unsigned char*)(sm + SM_LABS_OFF);
    int*            hist    = (int*)(sm + SM_HIST_OFF);
    int*            starts  = (int*)(sm + SM_START_OFF);
    int*            cursor  = (int*)(sm + SM_CUR_OFF);
    float*          wloss   = (float*)(sm + SM_WLOSS_OFF);
    int*            wtot    = (int*)(sm + SM_WTOT_OFF);
    unsigned int*   tick    = (unsigned int*)(sm + SM_TICK_OFF);

    const int tid  = threadIdx.x;
    const int lane = tid & 31;
    const int wid  = tid >> 5;
    const int b    = blockIdx.x / NTILES;
    const int t0   = (blockIdx.x % NTILES) * TILE_T;

    if (tid < CC) hist[tid] = 0;
    __syncthreads();

    // Labels for this tile + histogram (mask keeps smem safe under any dtype surprise)
    for (int i = tid; i < TILE_T; i += THREADS) {
        int l = label[b * TT + t0 + i] & (CC - 1);
        labs[i] = (unsigned char)l;
        atomicAdd(&hist[l], 1);
    }
    __syncthreads();

    // Parallel exclusive scan over 64 classes: shfl scan in warps 0/1 + carry
    {
        int v = (tid < CC) ? hist[tid] : 0;
        int incl = v;
        #pragma unroll
        for (int o = 1; o < 32; o <<= 1) {
            int n = __shfl_up_sync(0xffffffffu, incl, o);
            if (lane >= o) incl += n;
        }
        if (wid < 2 && lane == 31) wtot[wid] = incl;
        __syncthreads();
        if (tid < CC) {
            int excl = incl - v + (wid == 1 ? wtot[0] : 0);
            starts[tid] = excl;
            cursor[tid] = excl;
        }
        __syncthreads();
    }

    // Counting-sort scatter: order[] holds tile-local t indices grouped by class
    for (int i = tid; i < TILE_T; i += THREADS) {
        int pos = atomicAdd(&cursor[labs[i]], 1);
        order[pos] = (unsigned short)i;
    }

    // Global counts — once per block
    if (tid < CC) atomicAdd(&g_count[tid], hist[tid]);

    float lossacc = 0.0f;

    for (int ch = 0; ch < NCH; ch++) {
        __syncthreads();
        // Stage [DCH x TILE_T] chunk via float4 LDG, 8-deep register staging for
        // guaranteed MLP (8 x 512B in flight per warp). Transposed store to
        // tile[t*33 + dd] (4-way STS conflict; negligible vs DRAM latency win).
        const float4* f4base = (const float4*)
            (feature + ((long long)b * DD + ch * DCH) * TT + t0);
        #pragma unroll
        for (int h = 0; h < 2; h++) {
            float4 v[8];
            #pragma unroll
            for (int k = 0; k < 8; k++) {
                int f = tid + (h * 8 + k) * THREADS;   // 0..4095
                v[k] = f4base[(f >> 7) * (TT / 4) + (f & 127)];
            }
            #pragma unroll
            for (int k = 0; k < 8; k++) {
                int f  = tid + (h * 8 + k) * THREADS;
                int dd = f >> 7;
                int t  = (f & 127) * 4;
                tile[(t + 0) * PITCH + dd] = v[k].x;
                tile[(t + 1) * PITCH + dd] = v[k].y;
                tile[(t + 2) * PITCH + dd] = v[k].z;
                tile[(t + 3) * PITCH + dd] = v[k].w;
            }
        }
        __syncthreads();

        // Per-class register accumulation. Warp w owns classes w, w+8, ...
        // Lane = d-within-chunk; tile reads are conflict-free, order reads broadcast.
        for (int c = wid; c < CC; c += NWARP) {
            const int   m   = hist[c];
            const int   st  = starts[c];
            const float cen = centers[c * DD + ch * DCH + lane];
            float s0 = 0.0f, s1 = 0.0f;
            float l0 = 0.0f, l1 = 0.0f;
            int j = 0;
            for (; j + 1 < m; j += 2) {
                int ta = order[st + j];
                int tb = order[st + j + 1];
                float va = tile[ta * PITCH + lane];
                float vb = tile[tb * PITCH + lane];
                s0 += va; s1 += vb;
                float da = va - cen, db = vb - cen;
                l0 += da * da; l1 += db * db;
            }
            if (j < m) {
                int ta = order[st + j];
                float va = tile[ta * PITCH + lane];
                s0 += va;
                float da = va - cen;
                l0 += da * da;
            }
            lossacc += l0 + l1;
            atomicAdd(&g_S[c * DD + ch * DCH + lane], s0 + s1);
        }
    }

    // Loss reduction: lane -> warp -> block -> global
    #pragma unroll
    for (int o = 16; o > 0; o >>= 1)
        lossacc += __shfl_xor_sync(0xffffffffu, lossacc, o);
    if (lane == 0) wloss[wid] = lossacc;
    __syncthreads();
    if (tid == 0) {
        float s = 0.0f;
        #pragma unroll
        for (int w = 0; w < NWARP; w++) s += wloss[w];
        atomicAdd(&g_loss, s);
    }

    // ---- Last-block finalize (fused; removes init/finalize launches) ----
    __threadfence();
    if (tid == 0) tick[0] = atomicAdd(&g_done, 1u);
    __syncthreads();
    if (tick[0] == GRID - 1) {
        __threadfence();  // all other blocks' atomics are globally visible
        if (tid == 0) out[0] = g_loss / 33554432.0f;   // N*D
        for (int i = tid; i < CC * DD; i += THREADS) {
            int   c   = i >> 7;            // i / DD
            int   cnt = g_count[c];
            float d   = (cnt > 0) ? (centers[i] - __fdividef(g_S[i], (float)cnt))
                                  : 0.0f;
            out[1 + i] = d;
            g_S[i] = 0.0f;                 // reset for next replay
        }
        __syncthreads();
        if (tid < CC) g_count[tid] = 0;
        if (tid == 0) { g_loss = 0.0f; g_done = 0u; }
    }
}

extern "C" void kernel_launch(void* const* d_in, const int* in_sizes, int n_in,
                              void* d_out, int out_size) {
    // Bind inputs by element count (robust to metadata ordering):
    //   feature 33554432, label 262144, centers 8192
    const float* feature = 0;
    const int*   label   = 0;
    const float* centers = 0;
    for (int i = 0; i < n_in; i++) {
        if (in_sizes[i] == BB * DD * TT)      feature = (const float*)d_in[i];
        else if (in_sizes[i] == BB * TT)      label   = (const int*)d_in[i];
        else if (in_sizes[i] == CC * DD)      centers = (const float*)d_in[i];
    }
    float* out = (float*)d_out;
    (void)out_size;

    cudaFuncSetAttribute(cl_fused_kernel,
                         cudaFuncAttributeMaxDynamicSharedMemorySize, SM_TOTAL);

    cl_fused_kernel<<<GRID, THREADS, SM_TOTAL>>>(feature, label, centers, out);
}

// round 5
// speedup vs baseline: 2.0942x; 1.6819x over previous
#include <cuda_runtime.h>

// Problem constants
#define BB 128
#define DD 128
#define TT 2048
#define CC 64
#define TILE_T 512
#define NTILES 4
#define DCH 32
#define NCH 4
#define THREADS 512
#define NWARP (THREADS / 32)     // 16
#define PITCH 33
#define GRID (BB * NTILES)       // 512
#define NREP 4                   // g_S replicas to spread L2 atomic conflicts

// Scratch (allocation-free; self-reset each run so graph replays are identical)
__device__ float        g_S[NREP][CC * DD];
__device__ float        g_loss;
__device__ int          g_count[CC];
__device__ unsigned int g_done;

// Dynamic smem layout (bytes)
#define SM_TILE_OFF   0
#define SM_TILE_BYTES (TILE_T * PITCH * 4)                 // 67584
#define SM_ORDER_OFF  (SM_TILE_OFF + SM_TILE_BYTES)
#define SM_LABS_OFF   (SM_ORDER_OFF + TILE_T * 2)
#define SM_HIST_OFF   (SM_LABS_OFF + TILE_T)
#define SM_START_OFF  (SM_HIST_OFF + CC * 4)
#define SM_CUR_OFF    (SM_START_OFF + CC * 4)
#define SM_WRED_OFF   (SM_CUR_OFF + CC * 4)
#define SM_WTOT_OFF   (SM_WRED_OFF + NWARP * 4)
#define SM_TICK_OFF   (SM_WTOT_OFF + 8)
#define SM_TOTAL      (SM_TICK_OFF + 4)

__global__ __launch_bounds__(THREADS, 2)
void cl_fused_kernel(const float* __restrict__ feature,
                     const int* __restrict__ label,
                     const float* __restrict__ centers,
                     float* __restrict__ out) {
    extern __shared__ char sm[];
    float*          tile    = (float*)(sm + SM_TILE_OFF);
    unsigned short* order   = (unsigned short*)(sm + SM_ORDER_OFF);
    unsigned char*  labs    = (unsigned char*)(sm + SM_LABS_OFF);
    int*            hist    = (int*)(sm + SM_HIST_OFF);
    int*            starts  = (int*)(sm + SM_START_OFF);
    int*            cursor  = (int*)(sm + SM_CUR_OFF);
    float*          wred    = (float*)(sm + SM_WRED_OFF);
    int*            wtot    = (int*)(sm + SM_WTOT_OFF);
    unsigned int*   tick    = (unsigned int*)(sm + SM_TICK_OFF);

    const int tid  = threadIdx.x;
    const int lane = tid & 31;
    const int wid  = tid >> 5;
    const int b    = blockIdx.x >> 2;           // / NTILES
    const int t0   = (blockIdx.x & 3) * TILE_T;
    const int rep  = blockIdx.x & (NREP - 1);

    // Per-thread load geometry: t4 fixed, dd = dd0 + 4k for k=0..7
    const int t4  = tid & 127;
    const int dd0 = tid >> 7;                   // 0..3
    const int sw  = t4 & 31;                    // swizzle key (== lane)
    const int trow = t4 * (4 * PITCH);          // (4*t4)*33

    if (tid < CC) hist[tid] = 0;
    __syncthreads();

    // Labels + histogram (mask keeps smem safe under any dtype surprise)
    if (tid < TILE_T) {
        int l = label[b * TT + t0 + tid] & (CC - 1);
        labs[tid] = (unsigned char)l;
        atomicAdd(&hist[l], 1);
    }
    __syncthreads();

    // Exclusive scan over 64 classes (warps 0/1 shfl scan + carry)
    {
        int v = (tid < CC) ? hist[tid] : 0;
        int incl = v;
        #pragma unroll
        for (int o = 1; o < 32; o <<= 1) {
            int n = __shfl_up_sync(0xffffffffu, incl, o);
            if (lane >= o) incl += n;
        }
        if (wid < 2 && lane == 31) wtot[wid] = incl;
        __syncthreads();
        if (tid < CC) {
            int excl = incl - v + (wid == 1 ? wtot[0] : 0);
            starts[tid] = excl;
            cursor[tid] = excl;
        }
        __syncthreads();
    }

    // Counting-sort scatter
    if (tid < TILE_T) {
        int pos = atomicAdd(&cursor[labs[tid]], 1);
        order[pos] = (unsigned short)tid;
    }
    if (tid < CC) atomicAdd(&g_count[tid], hist[tid]);

    float sumsq = 0.0f;
    float4 v[8];

    // Prefetch chunk 0 (8 float4 per thread; lanes consecutive t4 -> coalesced 512B)
    {
        const float4* f4 = (const float4*)feature
            + ((long long)b * DD) * (TT / 4) + (t0 >> 2) + t4;
        #pragma unroll
        for (int k = 0; k < 8; k++)
            v[k] = f4[(long long)(dd0 + 4 * k) * (TT / 4)];
    }

    for (int ch = 0; ch < NCH; ch++) {
        __syncthreads();   // tile free (previous compute done)

        // Store to XOR-swizzled tile: addr = (4*t4+j)*33 + (dd ^ (t4&31)).
        // Conflict-free for these stores AND for lane=dd compute reads.
        #pragma unroll
        for (int k = 0; k < 8; k++) {
            int col = (dd0 + 4 * k) ^ sw;
            tile[trow + 0 * PITCH + col] = v[k].x;
            tile[trow + 1 * PITCH + col] = v[k].y;
            tile[trow + 2 * PITCH + col] = v[k].z;
            tile[trow + 3 * PITCH + col] = v[k].w;
            sumsq = fmaf(v[k].x, v[k].x, sumsq);
            sumsq = fmaf(v[k].y, v[k].y, sumsq);
            sumsq = fmaf(v[k].z, v[k].z, sumsq);
            sumsq = fmaf(v[k].w, v[k].w, sumsq);
        }
        __syncthreads();   // tile ready

        // Issue next chunk's loads now; DRAM latency hides behind the gather below.
        if (ch < NCH - 1) {
            const float4* f4 = (const float4*)feature
                + ((long long)b * DD + (ch + 1) * DCH) * (TT / 4) + (t0 >> 2) + t4;
            #pragma unroll
            for (int k = 0; k < 8; k++)
                v[k] = f4[(long long)(dd0 + 4 * k) * (TT / 4)];
        }

        // Per-class sums. Warp w owns classes w, w+16, w+32, w+48. Lane = d.
        float* gS = &g_S[rep][ch * DCH + lane];
        for (int c = wid; c < CC; c += NWARP) {
            const int m  = hist[c];
            const int st = starts[c];
            float s0 = 0.0f, s1 = 0.0f;
            int j = 0;
            for (; j + 1 < m; j += 2) {
                int ta = order[st + j];
                int tb = order[st + j + 1];
                s0 += tile[ta * PITCH + (lane ^ ((ta >> 2) & 31))];
                s1 += tile[tb * PITCH + (lane ^ ((tb >> 2) & 31))];
            }
            if (j < m) {
                int ta = order[st + j];
                s0 += tile[ta * PITCH + (lane ^ ((ta >> 2) & 31))];
            }
            atomicAdd(gS + c * DD, s0 + s1);
        }
    }

    // sumsq reduction: lane -> warp -> block -> global
    #pragma unroll
    for (int o = 16; o > 0; o >>= 1)
        sumsq += __shfl_xor_sync(0xffffffffu, sumsq, o);
    if (lane == 0) wred[wid] = sumsq;
    __syncthreads();
    if (tid == 0) {
        float s = 0.0f;
        #pragma unroll
        for (int w = 0; w < NWARP; w++) s += wred[w];
        atomicAdd(&g_loss, s);
    }

    // ---- Last-block finalize ----
    __threadfence();
    if (tid == 0) tick[0] = atomicAdd(&g_done, 1u);
    __syncthreads();
    if (tick[0] == GRID - 1) {
        __threadfence();
        float part = 0.0f;
        for (int i = tid; i < CC * DD; i += THREADS) {
            float s = g_S[0][i] + g_S[1][i] + g_S[2][i] + g_S[3][i];
            int   c   = i >> 7;
            int   cnt = g_count[c];
            float cen = centers[i];
            out[1 + i] = (cnt > 0) ? (cen - __fdividef(s, (float)cnt)) : 0.0f;
            // loss cross terms: cnt*cen^2 - 2*s*cen
            part += cen * ((float)cnt * cen - 2.0f * s);
            g_S[0][i] = 0.0f; g_S[1][i] = 0.0f; g_S[2][i] = 0.0f; g_S[3][i] = 0.0f;
        }
        #pragma unroll
        for (int o = 16; o > 0; o >>= 1)
            part += __shfl_xor_sync(0xffffffffu, part, o);
        if (lane == 0) wred[wid] = part;
        __syncthreads();
        if (tid == 0) {
            float t = 0.0f;
            #pragma unroll
            for (int w = 0; w < NWARP; w++) t += wred[w];
            out[0] = (g_loss + t) / 33554432.0f;   // / (N*D)
            g_loss = 0.0f; g_done = 0u;
        }
        if (tid < CC) g_count[tid] = 0;
    }
}

extern "C" void kernel_launch(void* const* d_in, const int* in_sizes, int n_in,
                              void* d_out, int out_size) {
    // Bind inputs by element count (robust to metadata ordering)
    const float* feature = 0;
    const int*   label   = 0;
    const float* centers = 0;
    for (int i = 0; i < n_in; i++) {
        if (in_sizes[i] == BB * DD * TT)      feature = (const float*)d_in[i];
        else if (in_sizes[i] == BB * TT)      label   = (const int*)d_in[i];
        else if (in_sizes[i] == CC * DD)      centers = (const float*)d_in[i];
    }
    float* out = (float*)d_out;
    (void)out_size;

    cudaFuncSetAttribute(cl_fused_kernel,
                         cudaFuncAttributeMaxDynamicSharedMemorySize, SM_TOTAL);

    cl_fused_kernel<<<GRID, THREADS, SM_TOTAL>>>(feature, label, centers, out);
}